// round 6
// baseline (speedup 1.0000x reference)
#include <cuda_runtime.h>

namespace {
constexpr int Hn = 1024;   // time steps

__device__ __forceinline__ float tanh_fast(float x){ float r; asm("tanh.approx.f32 %0, %1;" : "=f"(r) : "f"(x)); return r; }
__device__ __forceinline__ float ex2_fast (float x){ float r; asm("ex2.approx.ftz.f32 %0, %1;" : "=f"(r) : "f"(x)); return r; }
__device__ __forceinline__ float lg2_fast (float x){ float r; asm("lg2.approx.ftz.f32 %0, %1;" : "=f"(r) : "f"(x)); return r; }
__device__ __forceinline__ float rcp_fast (float x){ float r; asm("rcp.approx.ftz.f32 %0, %1;" : "=f"(r) : "f"(x)); return r; }
// softplus given pre-scaled (log2e) argument: log2(1 + 2^y)
__device__ __forceinline__ float sp_pre(float y){ return lg2_fast(1.0f + ex2_fast(y)); }
__device__ __forceinline__ float shflx(float v, int m){ return __shfl_xor_sync(0xffffffffu, v, m); }
__device__ __forceinline__ float shfli(float v, int s){ return __shfl_sync(0xffffffffu, v, s); }
}

// ONE battery per warp (32 lanes). Lane owns hp units {lane+32k, k<4} and hr
// units {lane+32k, k<2}. 1024 warps -> 2 warps/SMSP: the second warp's issue
// stream fills the first warp's dependency-stall bubbles (R5 showed a single
// warp leaves ~55% of issue slots idle).
__global__ void __launch_bounds__(256, 1) dci_rollout(
    const float* __restrict__ gI, const float* __restrict__ gT, const float* __restrict__ soc0,
    const float* __restrict__ W1p, const float* __restrict__ b1p,
    const float* __restrict__ W2p, const float* __restrict__ b2p,
    const float* __restrict__ W1r, const float* __restrict__ b1r,
    const float* __restrict__ W2r, const float* __restrict__ b2r,
    float* __restrict__ out)
{
    const int lane = threadIdx.x & 31;
    const int bat  = (blockIdx.x * blockDim.x + threadIdx.x) >> 5;

    constexpr float LOG2E = 1.4426950408889634f;
    constexpr float LN2   = 0.6931471805599453f;
    constexpr float EPS   = 1e-6f;

    // --- weights into registers; W2 param columns pre-scaled by log2e ---
    float w0[4], w1[4], w2[4], wb[4];
    float wx[4], wy[4], wz[4], wq[4];
#pragma unroll
    for (int k = 0; k < 4; ++k) {
        int u = lane + 32 * k;
        w0[k] = W1p[u]; w1[k] = W1p[128 + u]; w2[k] = W1p[256 + u]; wb[k] = b1p[u];
        float4 wp = reinterpret_cast<const float4*>(W2p)[u];   // [R0,R1,C1,Q] row u
        wx[k] = wp.x * LOG2E; wy[k] = wp.y * LOG2E; wz[k] = wp.z * LOG2E; wq[k] = wp.w * LOG2E;
    }
    float q0[2], q1[2], q2[2], qb[2], qw[2];
#pragma unroll
    for (int k = 0; k < 2; ++k) {
        int u = lane + 32 * k;
        q0[k] = W1r[u]; q1[k] = W1r[64 + u]; q2[k] = W1r[128 + u]; qb[k] = b1r[u];
        qw[k] = W2r[u];
    }
    float4 b2 = *reinterpret_cast<const float4*>(b2p);
    // biases pre-scaled (log2e for softplus args), divided by 32 per-lane
    const float bx32 = b2.x * (LOG2E / 32.0f);
    const float by32 = b2.y * (LOG2E / 32.0f);
    const float bz32 = b2.z * (LOG2E / 32.0f);
    const float bq32 = b2.w * (LOG2E / 32.0f);
    const float br32 = b2r[0] * (1.0f / 32.0f);

    // packed-reduce lane role: q = lane&3 selects which quantity this lane
    // carries after stage 2 (0:R0, 1:R1, 2:C1, 3:resid)
    const int   qq    = lane & 3;
    const float sclq  = (qq == 0) ? 0.01f * LN2 : (qq == 1) ? 0.02f * LN2 : 2000.0f * LN2;
    const bool  isres = (qq == 3);
    const bool  oddq  = (lane & 1) != 0;
    const bool  hiq   = (lane & 2) != 0;

    float s0  = soc0[bat];
    float soc = (s0 == s0) ? s0 : 0.8f;   // NaN -> 0.8
    float v1  = 0.0f;

    const float* Ib = gI + bat * Hn;
    const float* Tb = gT + bat * Hn;
    float It  = __ldg(Ib), Tt = __ldg(Tb);
    float cIt = It * (-1.0f / 3600.0f);
    float vkeep = 0.0f;
    float* orow = out + bat * Hn;

    // pipeline state: deferred V_pred(t-1). t=-1 dummy: h=0, IP=0 -> v1 no-op.
    float hA[4], hB[4];
#pragma unroll
    for (int k = 0; k < 4; ++k) { hA[k] = 0.0f; hB[k] = 0.0f; }
    float socInP = 0.0f, IP = 0.0f, TP = 0.0f;

    auto body = [&](float* hP, float* hN, int t) {
        const int tn = (t + 1) & (Hn - 1);      // wrap: in-bounds, unused at end
        const float In = __ldg(Ib + tn);
        const float Tn = __ldg(Tb + tn);

        // ---- off partials from h_{t-1} (ready at iteration start) ----
        float p0 = fmaf(hP[0], wx[0], bx32);
        float p1 = fmaf(hP[0], wy[0], by32);
        float p2 = fmaf(hP[0], wz[0], bz32);
#pragma unroll
        for (int k = 1; k < 4; ++k) {
            p0 = fmaf(hP[k], wx[k], p0);
            p1 = fmaf(hP[k], wy[k], p1);
            p2 = fmaf(hP[k], wz[k], p2);
        }
        // hr head (prev inputs)
        float pr = br32;
#pragma unroll
        for (int k = 0; k < 2; ++k) {
            float pre = fmaf(IP, q1[k], fmaf(TP, q2[k], qb[k]));
            float hrk = tanh_fast(fmaf(socInP, q0[k], pre));
            pr = fmaf(hrk, qw[k], pr);
        }

        // ---- packed 4-quantity reduce (off-critical) ----
        // stage 1 (xor 1): fold {p0,p1} and {p2,pr}
        float sA = p0 + shflx(p0, 1);
        float sB = p1 + shflx(p1, 1);
        float sC = p2 + shflx(p2, 1);
        float sD = pr + shflx(pr, 1);
        float u  = oddq ? sB : sA;
        float v  = oddq ? sD : sC;
        // stage 2 (xor 2): fold {u,v}
        float su = u + shflx(u, 2);
        float sv = v + shflx(v, 2);
        float w  = hiq ? sv : su;       // lane carries quantity (lane&3)
        // stages 3-5: shared single-value butterfly
        w += shflx(w, 4);
        w += shflx(w, 8);
        w += shflx(w, 16);
        // per-lane finalize: softplus+scale for params, raw for resid
        float fin = isres ? w : fmaf(sp_pre(w), sclq, EPS);

        // ---- critical: preact + 4 tanh for step t ----
#pragma unroll
        for (int k = 0; k < 4; ++k) {
            float pre = fmaf(It, w1[k], fmaf(Tt, w2[k], wb[k]));
            hN[k] = tanh_fast(fmaf(soc, w0[k], pre));
        }
        // Q partial tree + 5-stage butterfly
        float t0 = fmaf(hN[0], wq[0], bq32);
        float t1 = hN[1] * wq[1];
        float t2 = hN[2] * wq[2];
        float t3 = hN[3] * wq[3];
        float p3 = (t0 + t1) + (t2 + t3);
        p3 += shflx(p3, 1);
        p3 += shflx(p3, 2);
        p3 += shflx(p3, 4);
        p3 += shflx(p3, 8);
        p3 += shflx(p3, 16);

        float Q    = fmaf(sp_pre(p3), 5.0f * LN2, EPS);
        float rq   = rcp_fast(Q);
        float socn = __saturatef(fmaf(cIt, rq, soc));

        // ---- off consumers: gather params, v1, V_pred(t-1), store ----
        float R0    = shfli(fin, 0);
        float R1    = shfli(fin, 1);
        float C1    = shfli(fin, 2);
        float resid = shfli(fin, 3);

        float invRC = rcp_fast(R1 * C1);
        float invC1 = invRC * R1;                            // 1/C1 = R1/(R1*C1)
        float v1n = fmaf(IP, invC1, fmaf(-v1, invRC, v1));   // v1 - v1/(R1C1) + I/C1
        float ocv = fmaf(fmaf(fmaf(0.3f, soc, -0.5f), soc, 1.2f), soc, 3.0f);
        float Vp  = (ocv - fmaf(IP, R0, v1n)) + resid;       // ocv - I*R0 - v1 + resid

        const int tp = t - 1;
        if ((tp & 31) == lane)          vkeep = Vp;
        if (t > 0 && (tp & 31) == 31)   orow[(tp & ~31) + lane] = vkeep;
        v1 = v1n;

        // rotate scalar state
        socInP = soc; IP = It; TP = Tt;
        soc = socn;
        It = In; Tt = Tn; cIt = In * (-1.0f / 3600.0f);
    };

#pragma unroll 1
    for (int t = 0; t < Hn; t += 2) {
        body(hA, hB, t);
        body(hB, hA, t + 1);
    }

    // ================= epilogue: V_pred for t = 1023 (h in hA) =================
    {
        float p0 = fmaf(hA[0], wx[0], bx32);
        float p1 = fmaf(hA[0], wy[0], by32);
        float p2 = fmaf(hA[0], wz[0], bz32);
#pragma unroll
        for (int k = 1; k < 4; ++k) {
            p0 = fmaf(hA[k], wx[k], p0);
            p1 = fmaf(hA[k], wy[k], p1);
            p2 = fmaf(hA[k], wz[k], p2);
        }
        float pr = br32;
#pragma unroll
        for (int k = 0; k < 2; ++k) {
            float pre = fmaf(IP, q1[k], fmaf(TP, q2[k], qb[k]));
            float hrk = tanh_fast(fmaf(socInP, q0[k], pre));
            pr = fmaf(hrk, qw[k], pr);
        }
        float sA = p0 + shflx(p0, 1);
        float sB = p1 + shflx(p1, 1);
        float sC = p2 + shflx(p2, 1);
        float sD = pr + shflx(pr, 1);
        float u  = oddq ? sB : sA;
        float v  = oddq ? sD : sC;
        float su = u + shflx(u, 2);
        float sv = v + shflx(v, 2);
        float w  = hiq ? sv : su;
        w += shflx(w, 4);
        w += shflx(w, 8);
        w += shflx(w, 16);
        float fin = isres ? w : fmaf(sp_pre(w), sclq, EPS);

        float R0    = shfli(fin, 0);
        float R1    = shfli(fin, 1);
        float C1    = shfli(fin, 2);
        float resid = shfli(fin, 3);

        float invRC = rcp_fast(R1 * C1);
        float invC1 = invRC * R1;
        float v1n = fmaf(IP, invC1, fmaf(-v1, invRC, v1));
        float ocv = fmaf(fmaf(fmaf(0.3f, soc, -0.5f), soc, 1.2f), soc, 3.0f);
        float Vp  = (ocv - fmaf(IP, R0, v1n)) + resid;
        if (lane == 31) vkeep = Vp;              // tp=1023: tp&31==31
        orow[992 + lane] = vkeep;
    }
}

extern "C" void kernel_launch(void* const* d_in, const int* in_sizes, int n_in,
                              void* d_out, int out_size)
{
    // inputs: V(unused), I, Tz, soc0, W1p, b1p, W2p, b2p, W1r, b1r, W2r, b2r
    const float* I    = (const float*)d_in[1];
    const float* Tz   = (const float*)d_in[2];
    const float* soc0 = (const float*)d_in[3];
    const float* W1p  = (const float*)d_in[4];
    const float* b1p  = (const float*)d_in[5];
    const float* W2p  = (const float*)d_in[6];
    const float* b2p  = (const float*)d_in[7];
    const float* W1r  = (const float*)d_in[8];
    const float* b1r  = (const float*)d_in[9];
    const float* W2r  = (const float*)d_in[10];
    const float* b2r  = (const float*)d_in[11];
    float* out = (float*)d_out;

    // 1024 warps = 1024 batteries (1/warp); 128 blocks x 256 threads
    // -> 8 warps/SM on 128 SMs = 2 warps per SMSP (mutual bubble-filling).
    dci_rollout<<<128, 256>>>(I, Tz, soc0, W1p, b1p, W2p, b2p,
                              W1r, b1r, W2r, b2r, out);
}